// round 17
// baseline (speedup 1.0000x reference)
#include <cuda_runtime.h>
#include <cuda_fp16.h>
#include <cstdint>

// VectorQuantizer: x (16,2048,256) f32, codebook (1024,256) f32.
// Outputs (concatenated f32 in d_out):
//   [0, N*D)        quantized = x + (cb[idx] - x)
//   [N*D, N*D+N)    indices (as float)
//   [N*D+N]         commitment loss = mean((cb[idx]-x)^2)
//
// fp16x2 (HFMA2, full-rate fma pipe) distance pass with codebook pre-scaled
// by 1024 -> per-row candidates within a safe margin -> exact fp32 refine
// (validated rounding sequence, lowest-index ties) + fused gather + loss.

#define DDIM    256
#define KCODES  1024
#define NROWS   32768

#define BM 128          // rows per block
#define BN 128          // codes per chunk
#define CAND_CAP 16
#define MARGIN 1.2e-2f  // > 2 * worst-case |d_fp16 - d_fp32| (~8.6e-3)
#define INV512 0.001953125f   // 2/1024 (undo e-scale inside the -2x.e term)

__device__ float  g_sx[NROWS];
__device__ float  g_se[KCODES];
__device__ double g_part[NROWS / 8];
__device__ __half g_xh[(size_t)NROWS * DDIM];   // x in fp16
__device__ __half g_eh[(size_t)KCODES * DDIM];  // 1024*e in fp16
__device__ int    g_cnt[NROWS];
__device__ int    g_cand[NROWS * CAND_CAP];

// ---------------------------------------------------------------------------
// Row sum-of-squares (exact fp32) + fp16 conversion. One warp per row.
// x rows -> g_xh (unscaled); codebook rows -> g_eh scaled by 1024.
// ---------------------------------------------------------------------------
__global__ void stats_kernel(const float* __restrict__ x,
                             const float* __restrict__ cb,
                             int N, int K) {
    int warp = (blockIdx.x * blockDim.x + threadIdx.x) >> 5;
    int lane = threadIdx.x & 31;
    if (warp >= N + K) return;
    float s = 0.0f;
    if (warp < N) {
        const float* src = x + (size_t)warp * DDIM;
        __half* dst = g_xh + (size_t)warp * DDIM;
#pragma unroll
        for (int i = 0; i < DDIM / 32; i++) {
            float v = src[lane + 32 * i];
            s = fmaf(v, v, s);
            dst[lane + 32 * i] = __float2half(v);
        }
    } else {
        const float* src = cb + (size_t)(warp - N) * DDIM;
        __half* dst = g_eh + (size_t)(warp - N) * DDIM;
#pragma unroll
        for (int i = 0; i < DDIM / 32; i++) {
            float v = src[lane + 32 * i];
            s = fmaf(v, v, s);
            dst[lane + 32 * i] = __float2half(v * 1024.0f);
        }
    }
#pragma unroll
    for (int off = 16; off; off >>= 1)
        s += __shfl_down_sync(0xffffffffu, s, off);
    if (lane == 0) {
        if (warp < N) g_sx[warp] = s;
        else          g_se[warp - N] = s;
    }
}

// ---------------------------------------------------------------------------
// HFMA2 distance pass + per-row min + candidate collection.
// 256 threads as 16x16 (ty,tx). Block tile 128 rows x 128 codes per chunk,
// 8 chunks. Thread tile 8 rows x 8 codes, INTERLEAVED: rows ty+16i, codes
// tx+16j (conflict-free LDS). K in 8 chunks of 32 dims; accumulate full
// K=256 in half2 (even/odd dim pair sums), fold to fp32 once per n0-chunk.
//   Xs2[row][kp]: half2 (x[2kp], x[2kp+1]), row stride 20 u32 (pad).
//   Es2[kp][code]: half2 (e'[2kp], e'[2kp+1]), kp-major.
// a-load: 2 addrs/warp (broadcast); b-load: 16 distinct banks x2 broadcast.
// ---------------------------------------------------------------------------
__global__ __launch_bounds__(256, 2)
void dist_kernel() {
    __shared__ __align__(16) __half2 Xs2[BM][20];   // 16 used + pad
    __shared__ __align__(16) __half2 Es2[16][BN];
    __shared__ float    sxs[BM];
    __shared__ float    ses[BN];
    __shared__ unsigned rmin[BM];
    __shared__ int      cnt[BM];
    __shared__ int      lst[BM * CAND_CAP];

    const int tid = threadIdx.x;
    const int tx  = tid & 15;
    const int ty  = tid >> 4;
    const int r0  = blockIdx.x * BM;

    if (tid < BM) {
        sxs[tid]  = g_sx[r0 + tid];
        rmin[tid] = 0x7f7fffffu;      // FLT_MAX bits (d ~ 256 > 0)
        cnt[tid]  = 0;
    }

    for (int n0 = 0; n0 < KCODES; n0 += BN) {
        __syncthreads();   // init / previous pass2 done before ses overwrite
        if (tid < BN) ses[tid] = g_se[n0 + tid];

        unsigned accu[8][8];
#pragma unroll
        for (int i = 0; i < 8; i++)
#pragma unroll
            for (int j = 0; j < 8; j++) accu[i][j] = 0u;

        for (int kt = 0; kt < 8; kt++) {
            const int kk = kt * 32;          // dim base of this chunk
            __syncthreads();
            // X tile: 128 rows x 16 half2 = 512 uint4. r = idx>>2, q = idx&3.
#pragma unroll
            for (int p = 0; p < 2; p++) {
                int idx = tid + p * 256;
                int r = idx >> 2, q = idx & 3;
                uint4 v = *(const uint4*)(g_xh + (size_t)(r0 + r) * DDIM + kk + q * 8);
                *(uint4*)&Xs2[r][q * 4] = v;
            }
            // E tile: 16 kp x 128 codes. q = idx>>7, code = idx&127 ->
            // scatter 4 half2 to Es2[q*4+m][code] (lanes hit distinct banks).
#pragma unroll
            for (int p = 0; p < 2; p++) {
                int idx = tid + p * 256;
                int q = idx >> 7, code = idx & 127;
                uint4 v = *(const uint4*)(g_eh + (size_t)(n0 + code) * DDIM + kk + q * 8);
                const __half2* pv = (const __half2*)&v;
#pragma unroll
                for (int m = 0; m < 4; m++) Es2[q * 4 + m][code] = pv[m];
            }
            __syncthreads();

#pragma unroll
            for (int kp = 0; kp < 16; kp++) {
                __half2 av[8], bv[8];
#pragma unroll
                for (int i = 0; i < 8; i++) av[i] = Xs2[ty + 16 * i][kp];
#pragma unroll
                for (int j = 0; j < 8; j++) bv[j] = Es2[kp][tx + 16 * j];
#pragma unroll
                for (int i = 0; i < 8; i++)
#pragma unroll
                    for (int j = 0; j < 8; j++) {
                        __half2 t = __hfma2(av[i], bv[j], *(__half2*)&accu[i][j]);
                        accu[i][j] = *(unsigned*)&t;
                    }
            }
        }

        // Epilogue pass 1: fold half2 -> f32 distance (in place), per-row min.
#pragma unroll
        for (int i = 0; i < 8; i++) {
            int row = ty + 16 * i;
            float t0 = sxs[row];
            float dm = 3.4e38f;
#pragma unroll
            for (int j = 0; j < 8; j++) {
                __half2 h = *(__half2*)&accu[i][j];
                float dot = __low2float(h) + __high2float(h);
                float dv = fmaf(-INV512, dot, t0 + ses[tx + 16 * j]);
                accu[i][j] = __float_as_uint(dv);
                dm = fminf(dm, dv);
            }
            atomicMin(&rmin[row], __float_as_uint(dm));
        }
        __syncthreads();
        // Epilogue pass 2: collect candidates within MARGIN of running min.
#pragma unroll
        for (int i = 0; i < 8; i++) {
            int row = ty + 16 * i;
            float thr = __uint_as_float(rmin[row]) + MARGIN;
#pragma unroll
            for (int j = 0; j < 8; j++) {
                float dv = __uint_as_float(accu[i][j]);
                if (dv <= thr) {
                    int pos = atomicAdd(&cnt[row], 1);
                    if (pos < CAND_CAP)
                        lst[row * CAND_CAP + pos] = n0 + tx + 16 * j;
                }
            }
        }
    }

    __syncthreads();
    if (tid < BM) {
        int row = r0 + tid;
        int c = cnt[tid];
        g_cnt[row] = c;
        int m = c < CAND_CAP ? c : CAND_CAP;
        for (int j = 0; j < m; j++)
            g_cand[row * CAND_CAP + j] = lst[tid * CAND_CAP + j];
    }
}

// ---------------------------------------------------------------------------
// Exact refine + fused gather. One warp per row. Refine is bit-identical to
// the validated fp32 formula: serial fmaf dot over d=0..255,
// d = fmaf(-2,dot,sx+se), lowest-index ties. Overflow -> full exact scan.
// Then gather quantized = x + (q - x) and emit per-BLOCK loss partials.
// ---------------------------------------------------------------------------
__device__ __forceinline__ float exact_dist(const float4* __restrict__ xr,
                                            const float* __restrict__ cb,
                                            float sx, int k) {
    const float4* er = (const float4*)(cb + (size_t)k * DDIM);
    float dot = 0.0f;
#pragma unroll 8
    for (int i = 0; i < DDIM / 4; i++) {
        float4 a = xr[i], b = er[i];
        dot = fmaf(a.x, b.x, dot);
        dot = fmaf(a.y, b.y, dot);
        dot = fmaf(a.z, b.z, dot);
        dot = fmaf(a.w, b.w, dot);
    }
    return fmaf(-2.0f, dot, sx + g_se[k]);
}

__global__ void refine_gather_kernel(const float* __restrict__ x,
                                     const float* __restrict__ cb,
                                     float* __restrict__ out_idx_f,
                                     float* __restrict__ out_q) {
    __shared__ double warp_s[8];
    int warp_in_blk = threadIdx.x >> 5;
    int row  = blockIdx.x * 8 + warp_in_blk;
    int lane = threadIdx.x & 31;

    const float4* xr = (const float4*)(x + (size_t)row * DDIM);
    float sx = g_sx[row];
    int c = g_cnt[row];

    float bd = 3.4e38f;
    int   bk = 0x7fffffff;
    if (c <= CAND_CAP) {
        if (lane < c) {
            int k = g_cand[row * CAND_CAP + lane];
            bd = exact_dist(xr, cb, sx, k);
            bk = k;
        }
    } else {
        for (int k = lane; k < KCODES; k += 32) {
            float d = exact_dist(xr, cb, sx, k);
            if (d < bd || (d == bd && k < bk)) { bd = d; bk = k; }
        }
    }
#pragma unroll
    for (int off = 16; off; off >>= 1) {
        float od = __shfl_down_sync(0xffffffffu, bd, off);
        int   ok = __shfl_down_sync(0xffffffffu, bk, off);
        if (od < bd || (od == bd && ok < bk)) { bd = od; bk = ok; }
    }
    bk = __shfl_sync(0xffffffffu, bk, 0);
    if (lane == 0) out_idx_f[row] = (float)bk;

    const float4* qr = (const float4*)(cb + (size_t)bk * DDIM);
    float4* orow = (float4*)(out_q + (size_t)row * DDIM);
    double s = 0.0;
#pragma unroll
    for (int i = 0; i < 2; i++) {
        float4 xv = xr[lane + 32 * i];
        float4 qv = qr[lane + 32 * i];
        float4 o;
        float e0 = qv.x - xv.x; o.x = xv.x + e0; s += (double)e0 * e0;
        float e1 = qv.y - xv.y; o.y = xv.y + e1; s += (double)e1 * e1;
        float e2 = qv.z - xv.z; o.z = xv.z + e2; s += (double)e2 * e2;
        float e3 = qv.w - xv.w; o.w = xv.w + e3; s += (double)e3 * e3;
        orow[lane + 32 * i] = o;
    }
#pragma unroll
    for (int off = 16; off; off >>= 1)
        s += __shfl_down_sync(0xffffffffu, s, off);
    if (lane == 0) warp_s[warp_in_blk] = s;
    __syncthreads();
    if (threadIdx.x == 0) {
        double bs = 0.0;
#pragma unroll
        for (int w = 0; w < 8; w++) bs += warp_s[w];
        g_part[blockIdx.x] = bs;
    }
}

__global__ void finalize_kernel(float* __restrict__ out_loss,
                                int nblocks, long long ND) {
    __shared__ double sm[256];
    double s = 0.0;
    for (int i = threadIdx.x; i < nblocks; i += 256) s += g_part[i];
    sm[threadIdx.x] = s;
    __syncthreads();
    for (int off = 128; off; off >>= 1) {
        if (threadIdx.x < off) sm[threadIdx.x] += sm[threadIdx.x + off];
        __syncthreads();
    }
    if (threadIdx.x == 0) *out_loss = (float)(sm[0] / (double)ND);
}

// ---------------------------------------------------------------------------
extern "C" void kernel_launch(void* const* d_in, const int* in_sizes, int n_in,
                              void* d_out, int out_size) {
    const float* x  = (const float*)d_in[0];
    const float* cb = (const float*)d_in[1];
    int N = in_sizes[0] / DDIM;   // 32768
    int K = in_sizes[1] / DDIM;   // 1024

    float* out   = (float*)d_out;
    float* out_q = out;
    float* out_i = out + (size_t)N * DDIM;
    float* out_l = out + (size_t)N * DDIM + N;

    stats_kernel<<<(N + K + 7) / 8, 256>>>(x, cb, N, K);
    dist_kernel<<<N / BM, 256>>>();
    int rg_blocks = N / 8;   // 4096
    refine_gather_kernel<<<rg_blocks, 256>>>(x, cb, out_i, out_q);
    finalize_kernel<<<1, 256>>>(out_l, rg_blocks, (long long)N * DDIM);
}